// round 5
// baseline (speedup 1.0000x reference)
#include <cuda_runtime.h>
#include <math.h>

// Problem constants (fixed by reference: B=32768, D=512)
#define BSZ 32768
#define DSZ 512
#define ROWS_PER_BLOCK 16
#define NBLOCKS (BSZ / ROWS_PER_BLOCK)   // 2048
#define NTHREADS 256
#define F4_PER_ROW (DSZ / 4)             // 128
#define ITERS ((ROWS_PER_BLOCK * F4_PER_ROW) / NTHREADS)  // 8

__device__ float g_partials[NBLOCKS];
__device__ int   g_count;   // zero-init; reset to 0 by last block each launch

__global__ void __launch_bounds__(NTHREADS)
fused_loss_kernel(const float4* __restrict__ inp,
                  const float4* __restrict__ lab,
                  const float*  __restrict__ ea,
                  const int*    __restrict__ attribute,
                  const float*  __restrict__ attribute_num,
                  float* __restrict__ out) {
    __shared__ float sw[ROWS_PER_BLOCK];
    __shared__ float sdata[NTHREADS];

    const int tid = threadIdx.x;
    const int row0 = blockIdx.x * ROWS_PER_BLOCK;

    // ---- per-row weights for this block's 16 rows (threads 0..15) ----
    if (tid < ROWS_PER_BLOCK) {
        int b = row0 + tid;
        float an[6];
        float s = 0.0f;
#pragma unroll
        for (int j = 0; j < 6; j++) { an[j] = attribute_num[j]; s += an[j]; }
        float attr_w = 0.0f;
#pragma unroll
        for (int j = 0; j < 6; j++) {
            attr_w += (attribute[b * 6 + j] == 1) ? (s / an[j]) : 0.0f;
        }
        float angle_w = 3.0f - cosf(ea[b * 3 + 0])
                             - cosf(ea[b * 3 + 1])
                             - cosf(ea[b * 3 + 2]);
        sw[tid] = angle_w * attr_w;
    }
    __syncthreads();

    // ---- main HBM-bound loop: 8 fully unrolled float4-pair iterations ----
    const int base = row0 * F4_PER_ROW + tid;    // float4 index
    const int wbase = tid >> 7;                  // 0 or 1 (128 float4/row)
    float acc = 0.0f;
#pragma unroll
    for (int k = 0; k < ITERS; k++) {
        int i = base + k * NTHREADS;
        float4 a = __ldcs(&inp[i]);
        float4 b = __ldcs(&lab[i]);
        float w = sw[k * 2 + wbase];             // compile-time smem index
        float dx = a.x - b.x;
        float dy = a.y - b.y;
        float dz = a.z - b.z;
        float dw = a.w - b.w;
        acc += w * (dx * dx + dy * dy + dz * dz + dw * dw);
    }

    // ---- block tree-reduce ----
    sdata[tid] = acc;
    __syncthreads();
#pragma unroll
    for (int off = NTHREADS / 2; off >= 32; off >>= 1) {
        if (tid < off) sdata[tid] += sdata[tid + off];
        __syncthreads();
    }
    if (tid < 32) {
        float v = sdata[tid];
#pragma unroll
        for (int off = 16; off > 0; off >>= 1)
            v += __shfl_down_sync(0xFFFFFFFF, v, off);
        if (tid == 0) g_partials[blockIdx.x] = v;
    }

    // ---- last-block-done final reduce (deterministic fixed-order sum) ----
    __shared__ bool is_last;
    if (tid == 0) {
        __threadfence();                          // publish g_partials
        int old = atomicAdd(&g_count, 1);
        is_last = (old == NBLOCKS - 1);
    }
    __syncthreads();
    if (!is_last) return;

    // this block reduces all 2048 partials in fixed order
    float v = 0.0f;
#pragma unroll
    for (int k = 0; k < NBLOCKS / NTHREADS; k++)  // 8 fixed-order terms
        v += g_partials[tid + k * NTHREADS];
    sdata[tid] = v;
    __syncthreads();
#pragma unroll
    for (int off = NTHREADS / 2; off >= 32; off >>= 1) {
        if (tid < off) sdata[tid] += sdata[tid + off];
        __syncthreads();
    }
    if (tid < 32) {
        float s2 = sdata[tid];
#pragma unroll
        for (int off = 16; off > 0; off >>= 1)
            s2 += __shfl_down_sync(0xFFFFFFFF, s2, off);
        if (tid == 0) {
            out[0] = s2 * (1.0f / (float)(BSZ * DSZ));
            g_count = 0;   // reset so graph replay is deterministic
        }
    }
}

// ---------------------------------------------------------------------------
// kernel_launch — input order: inp, label, ea, attribute, attribute_num,
// batch_size
// ---------------------------------------------------------------------------
extern "C" void kernel_launch(void* const* d_in, const int* in_sizes, int n_in,
                              void* d_out, int out_size) {
    const float* inp  = (const float*)d_in[0];
    const float* lab  = (const float*)d_in[1];
    const float* ea   = (const float*)d_in[2];
    const int*   attr = (const int*)d_in[3];
    const float* anum = (const float*)d_in[4];
    float* out = (float*)d_out;

    fused_loss_kernel<<<NBLOCKS, NTHREADS>>>((const float4*)inp,
                                             (const float4*)lab,
                                             ea, attr, anum, out);
}